// round 15
// baseline (speedup 1.0000x reference)
#include <cuda_runtime.h>
#include <cuda_bf16.h>
#include <cuda_fp16.h>
#include <mma.h>
#include <cstdint>

using namespace nvcuda;

#define B_  2
#define S_  2048
#define D_  2048
#define H_  16
#define HD_ 128
#define M_  (B_ * S_)      // 4096 token rows

// ---------------- scratch (device globals; no dynamic allocation) ----------------
__device__ __half g_h   [(size_t)M_ * D_];        // fp16 GEMM A operands
__device__ __half g_qkvh[(size_t)M_ * 3 * D_];    // fp16 qkv
__device__ __half g_attn[(size_t)M_ * D_];
__device__ float  g_x1  [(size_t)M_ * D_];
__device__ __half g_ffn [(size_t)M_ * 4 * D_];
// fp16 weight copies
__device__ __half g_wqkv[(size_t)3 * D_ * D_];
__device__ __half g_wout[(size_t)D_ * D_];
__device__ __half g_wfc1[(size_t)4 * D_ * D_];
__device__ __half g_wfc2[(size_t)D_ * 4 * D_];

#define QSCALE 0.08838834764831845f      // 1/sqrt(128)

// ---------------- cp.async helpers ----------------
__device__ __forceinline__ void cp_async16s(unsigned smem_dst, const void* gmem_src) {
    asm volatile("cp.async.cg.shared.global [%0], [%1], 16;\n" :: "r"(smem_dst), "l"(gmem_src));
}
__device__ __forceinline__ void cp_commit() { asm volatile("cp.async.commit_group;\n"); }
__device__ __forceinline__ void cp_wait0()  { asm volatile("cp.async.wait_group 0;\n"); }
__device__ __forceinline__ void cp_wait1()  { asm volatile("cp.async.wait_group 1;\n"); }

// ---------------- weight fp32 -> fp16 ----------------
__global__ void cvt_f2h_kernel(const float* __restrict__ in, __half* __restrict__ out, int n4) {
    int i = blockIdx.x * 256 + threadIdx.x;
    if (i >= n4) return;
    float4 v = ((const float4*)in)[i];
    ((__half2*)out)[i * 2]     = __floats2half2_rn(v.x, v.y);
    ((__half2*)out)[i * 2 + 1] = __floats2half2_rn(v.z, v.w);
}

// ---------------- rmsnorm (fp16 output) ----------------
__global__ void rmsnorm_kernel(const float* __restrict__ x, const float* __restrict__ g,
                               __half* __restrict__ out) {
    int row = blockIdx.x;
    const float* xr = x + (size_t)row * D_;
    __half* orow = out + (size_t)row * D_;
    float ss = 0.f;
    for (int i = threadIdx.x; i < D_; i += 256) { float v = xr[i]; ss += v * v; }
    __shared__ float red[8];
    #pragma unroll
    for (int o = 16; o > 0; o >>= 1) ss += __shfl_xor_sync(0xffffffffu, ss, o);
    if ((threadIdx.x & 31) == 0) red[threadIdx.x >> 5] = ss;
    __syncthreads();
    if (threadIdx.x < 8) {
        float v = red[threadIdx.x];
        #pragma unroll
        for (int o = 4; o > 0; o >>= 1) v += __shfl_xor_sync(0xffu, v, o);
        if (threadIdx.x == 0) red[0] = v;
    }
    __syncthreads();
    float inv = rsqrtf(red[0] / (float)D_ + 1e-6f);
    for (int i = threadIdx.x; i < D_; i += 256) orow[i] = __float2half(g[i] * xr[i] * inv);
}

// ---------------- fp16 GEMM: C[M,N] = epi(A[M,K] @ B[N,K]^T) ----------------
// Block tile 128xBN, BK=64 halfs, 3-stage cp.async pipeline.
// 8 warps (2 x 4); warp tile 64 x (BN/4); 16x16x16 half fragments, fp32 accum.
// ACT: 0 = float C + optional residual; 1 = tanh-gelu -> half C; 2 = plain -> half C.
#define GBM 128
#define GBK 64
#define GLD 72                            // halfs per smem row

template <int ACT, int BN>
__global__ __launch_bounds__(256, 1) void gemm_fp16(const __half* __restrict__ A,
                                                    const __half* __restrict__ Bm,
                                                    void* __restrict__ Cv,
                                                    const float* __restrict__ res,
                                                    int M, int N, int K) {
    constexpr int NWF = BN / 64;
    constexpr int A_ST = GBM * GLD;
    constexpr int B_ST = BN * GLD;
    constexpr int ST_H = A_ST + B_ST;

    extern __shared__ __half smem[];
    unsigned sbase = (unsigned)__cvta_generic_to_shared(smem);

    int tid = threadIdx.x, warp = tid >> 5;
    int wm = warp & 1, wn = warp >> 1;                 // 2 x 4
    int bm = blockIdx.y * GBM, bn = blockIdx.x * BN;

    wmma::fragment<wmma::accumulator, 16, 16, 16, float> acc[4][NWF];
    #pragma unroll
    for (int i = 0; i < 4; i++)
        #pragma unroll
        for (int j = 0; j < NWF; j++) wmma::fill_fragment(acc[i][j], 0.f);

    const int NT = K / GBK;

    auto load_tile = [&](int t) {
        int st = t % 3;
        unsigned a_s = sbase + (unsigned)(st * ST_H) * 2u;
        unsigned b_s = a_s + A_ST * 2u;
        int k0 = t * GBK;
        #pragma unroll
        for (int i = tid; i < GBM * 8; i += 256) {
            int r = i >> 3, c8 = i & 7;
            cp_async16s(a_s + (unsigned)(r * GLD + c8 * 8) * 2u,
                        &A[(size_t)(bm + r) * K + k0 + c8 * 8]);
        }
        #pragma unroll
        for (int i = tid; i < BN * 8; i += 256) {
            int r = i >> 3, c8 = i & 7;
            cp_async16s(b_s + (unsigned)(r * GLD + c8 * 8) * 2u,
                        &Bm[(size_t)(bn + r) * K + k0 + c8 * 8]);
        }
        cp_commit();
    };

    load_tile(0);
    if (NT > 1) load_tile(1);

    for (int t = 0; t < NT; t++) {
        if (t + 1 < NT) cp_wait1(); else cp_wait0();
        __syncthreads();
        if (t + 2 < NT) load_tile(t + 2);

        int st = t % 3;
        __half* As = smem + st * ST_H;
        __half* Bs = As + A_ST;

        #pragma unroll
        for (int kk = 0; kk < GBK; kk += 16) {
            wmma::fragment<wmma::matrix_a, 16, 16, 16, __half, wmma::row_major> af[4];
            wmma::fragment<wmma::matrix_b, 16, 16, 16, __half, wmma::col_major> bf[NWF];
            #pragma unroll
            for (int i = 0; i < 4; i++)
                wmma::load_matrix_sync(af[i], &As[(wm * 64 + i * 16) * GLD + kk], GLD);
            #pragma unroll
            for (int j = 0; j < NWF; j++)
                wmma::load_matrix_sync(bf[j], &Bs[(wn * (BN / 4) + j * 16) * GLD + kk], GLD);
            #pragma unroll
            for (int i = 0; i < 4; i++)
                #pragma unroll
                for (int j = 0; j < NWF; j++)
                    wmma::mma_sync(acc[i][j], af[i], bf[j], acc[i][j]);
        }
        __syncthreads();
    }

    // epilogue: stage through smem (float), fuse residual/gelu
    constexpr int SLD = BN + 4;
    float* stage = (float*)smem;
    #pragma unroll
    for (int i = 0; i < 4; i++)
        #pragma unroll
        for (int j = 0; j < NWF; j++)
            wmma::store_matrix_sync(&stage[(size_t)(wm * 64 + i * 16) * SLD + wn * (BN / 4) + j * 16],
                                    acc[i][j], SLD, wmma::mem_row_major);
    __syncthreads();
    for (int i = tid; i < GBM * (BN / 4); i += 256) {
        int r = i / (BN / 4), c4 = (i % (BN / 4)) << 2;
        float4 v = *(float4*)&stage[(size_t)r * SLD + c4];
        if (ACT == 1) {
            float* p = (float*)&v;
            #pragma unroll
            for (int e = 0; e < 4; e++) {
                float xx = p[e];
                float th = tanhf(0.7978845608028654f * (xx + 0.044715f * xx * xx * xx));
                p[e] = 0.5f * xx * (1.f + th);
            }
        }
        if (ACT == 1 || ACT == 2) {
            __half* Ch = (__half*)Cv;
            __half2* dst = (__half2*)&Ch[(size_t)(bm + r) * N + bn + c4];
            dst[0] = __floats2half2_rn(v.x, v.y);
            dst[1] = __floats2half2_rn(v.z, v.w);
        } else {
            if (res) {
                const float4 rv = *(const float4*)&res[(size_t)(bm + r) * N + bn + c4];
                v.x += rv.x; v.y += rv.y; v.z += rv.z; v.w += rv.w;
            }
            *(float4*)&((float*)Cv)[(size_t)(bm + r) * N + bn + c4] = v;
        }
    }
}

// ---------------- RoPE on fp16 qkv (fp32 math; q-scale folded in) ----------------
__global__ void rope_h_kernel(__half* __restrict__ qkv, const float* __restrict__ cs,
                              const float* __restrict__ sn) {
    int idx = blockIdx.x * 256 + threadIdx.x;
    if (idx >= M_ * H_ * 64) return;
    int d = idx & 63;
    int h = (idx >> 6) & 15;
    int row = idx >> 10;
    int s = row & (S_ - 1);
    float c0 = cs[s * HD_ + d],      s0 = sn[s * HD_ + d];
    float c1 = cs[s * HD_ + d + 64], s1 = sn[s * HD_ + d + 64];
    #pragma unroll
    for (int p = 0; p < 2; p++) {                 // p=0: q (scaled), p=1: k
        size_t base = (size_t)row * (3 * D_) + (size_t)p * D_ + h * HD_;
        float a = __half2float(qkv[base + d]);
        float b = __half2float(qkv[base + d + 64]);
        float o0 = a * c0 - b * s0;
        float o1 = b * c1 + a * s1;
        if (p == 0) { o0 *= QSCALE; o1 *= QSCALE; }
        qkv[base + d]      = __float2half(o0);
        qkv[base + d + 64] = __float2half(o1);
    }
}

// ---------------- flash attention (causal), fp16 MMA, fp32 softmax/accum ----------------
struct FaSmem {
    __half Qh[64][136];
    __half Kh[64][136];
    __half Vh[64][136];
    float  Sf[64][68];
    __half Ph[64][72];
    float  Os[64][128];
    float  Ot[64][132];
    float  mrow[64], lrow[64], alpha[64];
};

__global__ __launch_bounds__(256) void flash_kernel(const __half* __restrict__ qkv,
                                                    __half* __restrict__ attn) {
    extern __shared__ char smem_raw[];
    FaSmem& s = *reinterpret_cast<FaSmem*>(smem_raw);
    int b = blockIdx.z, h = blockIdx.y, q0 = blockIdx.x * 64;
    int tid = threadIdx.x, warp = tid >> 5;
    int wm = warp >> 1, wn = warp & 1;          // 4 x 2

    size_t qbase = ((size_t)(b * S_ + q0)) * (3 * D_) + h * HD_;
    for (int i = tid; i < 64 * 16; i += 256) {
        int r = i >> 4, c8 = (i & 15) << 3;
        *(uint4*)&s.Qh[r][c8] = *(const uint4*)&qkv[qbase + (size_t)r * (3 * D_) + c8];
    }
    for (int i = tid; i < 64 * 128; i += 256) ((float*)s.Os)[i] = 0.f;
    if (tid < 64) { s.mrow[tid] = -1e30f; s.lrow[tid] = 0.f; }

    size_t kbase = ((size_t)(b * S_)) * (3 * D_) + D_ + h * HD_;
    size_t vbase = kbase + D_;

    for (int j0 = 0; j0 <= q0; j0 += 64) {
        __syncthreads();   // prior iteration done (Ot consumed), first-iter init done
        for (int i = tid; i < 64 * 16; i += 256) {
            int r = i >> 4, c8 = (i & 15) << 3;
            *(uint4*)&s.Kh[r][c8] = *(const uint4*)&qkv[kbase + (size_t)(j0 + r) * (3 * D_) + c8];
            *(uint4*)&s.Vh[r][c8] = *(const uint4*)&qkv[vbase + (size_t)(j0 + r) * (3 * D_) + c8];
        }
        __syncthreads();

        // S = Q K^T  (64x64, K=128); warp tile 16x32
        wmma::fragment<wmma::accumulator, 16, 16, 16, float> accs[2];
        wmma::fill_fragment(accs[0], 0.f);
        wmma::fill_fragment(accs[1], 0.f);
        #pragma unroll
        for (int kk = 0; kk < 128; kk += 16) {
            wmma::fragment<wmma::matrix_a, 16, 16, 16, __half, wmma::row_major> af;
            wmma::load_matrix_sync(af, &s.Qh[wm * 16][kk], 136);
            #pragma unroll
            for (int j = 0; j < 2; j++) {
                wmma::fragment<wmma::matrix_b, 16, 16, 16, __half, wmma::col_major> bf;
                wmma::load_matrix_sync(bf, &s.Kh[wn * 32 + j * 16][kk], 136);
                wmma::mma_sync(accs[j], af, bf, accs[j]);
            }
        }
        wmma::store_matrix_sync(&s.Sf[wm * 16][wn * 32],      accs[0], 68, wmma::mem_row_major);
        wmma::store_matrix_sync(&s.Sf[wm * 16][wn * 32 + 16], accs[1], 68, wmma::mem_row_major);
        __syncthreads();

        // online softmax: 4 threads per row; write P as fp16
        {
            int r = tid >> 2, part = tid & 3;
            bool diag = (j0 == q0);
            float vals[16];
            float mx = -1e30f;
            #pragma unroll
            for (int c = 0; c < 16; c++) {
                int cc = part * 16 + c;
                float v = s.Sf[r][cc];
                if (diag && cc > r) v = -1e30f;
                vals[c] = v;
                mx = fmaxf(mx, v);
            }
            mx = fmaxf(mx, __shfl_xor_sync(0xffffffffu, mx, 1));
            mx = fmaxf(mx, __shfl_xor_sync(0xffffffffu, mx, 2));
            float newm = fmaxf(s.mrow[r], mx);
            float sum = 0.f;
            #pragma unroll
            for (int c = 0; c < 16; c++) {
                float p = (vals[c] <= -1e29f) ? 0.f : __expf(vals[c] - newm);
                s.Ph[r][part * 16 + c] = __float2half(p);
                sum += p;
            }
            sum += __shfl_xor_sync(0xffffffffu, sum, 1);
            sum += __shfl_xor_sync(0xffffffffu, sum, 2);
            if (part == 0) {
                float al = __expf(s.mrow[r] - newm);
                s.alpha[r] = al;
                s.lrow[r] = s.lrow[r] * al + sum;
                s.mrow[r] = newm;
            }
        }
        __syncthreads();

        // PV (64x128, K=64); warp tile 16x64 -> Ot scratch
        wmma::fragment<wmma::accumulator, 16, 16, 16, float> acco[4];
        #pragma unroll
        for (int j = 0; j < 4; j++) wmma::fill_fragment(acco[j], 0.f);
        #pragma unroll
        for (int kk = 0; kk < 64; kk += 16) {
            wmma::fragment<wmma::matrix_a, 16, 16, 16, __half, wmma::row_major> af;
            wmma::load_matrix_sync(af, &s.Ph[wm * 16][kk], 72);
            #pragma unroll
            for (int j = 0; j < 4; j++) {
                wmma::fragment<wmma::matrix_b, 16, 16, 16, __half, wmma::row_major> bf;
                wmma::load_matrix_sync(bf, &s.Vh[kk][wn * 64 + j * 16], 136);
                wmma::mma_sync(acco[j], af, bf, acco[j]);
            }
        }
        #pragma unroll
        for (int j = 0; j < 4; j++)
            wmma::store_matrix_sync(&s.Ot[wm * 16][wn * 64 + j * 16], acco[j], 132,
                                    wmma::mem_row_major);
        __syncthreads();

        for (int i = tid; i < 64 * 128; i += 256) {
            int r = i >> 7, c = i & 127;
            s.Os[r][c] = s.Os[r][c] * s.alpha[r] + s.Ot[r][c];
        }
    }
    __syncthreads();

    size_t obase = ((size_t)(b * S_ + q0)) * D_ + h * HD_;
    for (int i = tid; i < 64 * 128; i += 256) {
        int r = i >> 7, c = i & 127;
        attn[obase + (size_t)r * D_ + c] = __float2half(s.Os[r][c] / s.lrow[r]);
    }
}

// ---------------- launch ----------------
#define SMEM_BN(BN) (3 * (GBM * GLD + (BN) * GLD) * 2)

extern "C" void kernel_launch(void* const* d_in, const int* in_sizes, int n_in,
                              void* d_out, int out_size) {
    const float* x     = (const float*)d_in[0];
    const float* cs    = (const float*)d_in[1];
    const float* sn    = (const float*)d_in[2];
    const float* g1    = (const float*)d_in[3];
    const float* g2    = (const float*)d_in[4];
    const float* w_qkv = (const float*)d_in[5];
    const float* w_out = (const float*)d_in[6];
    const float* w_fc1 = (const float*)d_in[7];
    const float* w_fc2 = (const float*)d_in[8];
    float* out = (float*)d_out;

    __half *h, *qkvh, *attn, *ffn, *wq, *wo, *w1, *w2;
    float *x1;
    cudaGetSymbolAddress((void**)&h,    g_h);
    cudaGetSymbolAddress((void**)&qkvh, g_qkvh);
    cudaGetSymbolAddress((void**)&attn, g_attn);
    cudaGetSymbolAddress((void**)&x1,   g_x1);
    cudaGetSymbolAddress((void**)&ffn,  g_ffn);
    cudaGetSymbolAddress((void**)&wq,   g_wqkv);
    cudaGetSymbolAddress((void**)&wo,   g_wout);
    cudaGetSymbolAddress((void**)&w1,   g_wfc1);
    cudaGetSymbolAddress((void**)&w2,   g_wfc2);

    cudaFuncSetAttribute((const void*)gemm_fp16<2, 256>,
                         cudaFuncAttributeMaxDynamicSharedMemorySize, SMEM_BN(256));
    cudaFuncSetAttribute((const void*)gemm_fp16<1, 256>,
                         cudaFuncAttributeMaxDynamicSharedMemorySize, SMEM_BN(256));
    cudaFuncSetAttribute((const void*)gemm_fp16<0, 128>,
                         cudaFuncAttributeMaxDynamicSharedMemorySize, SMEM_BN(128));
    cudaFuncSetAttribute((const void*)flash_kernel,
                         cudaFuncAttributeMaxDynamicSharedMemorySize, (int)sizeof(FaSmem));

    // 0) weights -> fp16 copies
    cvt_f2h_kernel<<<(3 * D_ * D_ / 4 + 255) / 256, 256>>>(w_qkv, wq, 3 * D_ * D_ / 4);
    cvt_f2h_kernel<<<(D_ * D_ / 4 + 255) / 256, 256>>>(w_out, wo, D_ * D_ / 4);
    cvt_f2h_kernel<<<(4 * D_ * D_ / 4 + 255) / 256, 256>>>(w_fc1, w1, 4 * D_ * D_ / 4);
    cvt_f2h_kernel<<<(4 * D_ * D_ / 4 + 255) / 256, 256>>>(w_fc2, w2, 4 * D_ * D_ / 4);

    // 1) rmsnorm1 -> fp16 h
    rmsnorm_kernel<<<M_, 256>>>(x, g1, h);
    // 2) qkv = h @ wq^T -> fp16 (plain epilogue)
    gemm_fp16<2, 256><<<dim3(6144 / 256, M_ / GBM), 256, SMEM_BN(256)>>>(h, wq, (void*)qkvh,
                                                                         nullptr, M_, 3 * D_, D_);
    // 3) rope (+ q-scale) on fp16 qkv
    rope_h_kernel<<<(M_ * H_ * 64) / 256, 256>>>(qkvh, cs, sn);
    // 4) causal flash attention (fp16 in/out)
    flash_kernel<<<dim3(S_ / 64, H_, B_), 256, sizeof(FaSmem)>>>(qkvh, attn);
    // 5) x1 = x + attn @ wo^T   (BN=128: 512 CTAs, finer waves)
    gemm_fp16<0, 128><<<dim3(2048 / 128, M_ / GBM), 256, SMEM_BN(128)>>>(attn, wo, (void*)x1,
                                                                         x, M_, D_, D_);
    // 6) rmsnorm2 -> fp16 h
    rmsnorm_kernel<<<M_, 256>>>(x1, g2, h);
    // 7) ffn = gelu(h @ w1^T) -> fp16
    gemm_fp16<1, 256><<<dim3(8192 / 256, M_ / GBM), 256, SMEM_BN(256)>>>(h, w1, (void*)ffn,
                                                                         nullptr, M_, 4 * D_, D_);
    // 8) out = x1 + ffn @ w2^T   (BN=128: 512 CTAs)
    gemm_fp16<0, 128><<<dim3(2048 / 128, M_ / GBM), 256, SMEM_BN(128)>>>(ffn, w2, (void*)out,
                                                                         x1, M_, D_, 4 * D_);
}

// round 17
// speedup vs baseline: 1.1428x; 1.1428x over previous
#include <cuda_runtime.h>
#include <cuda_bf16.h>
#include <cuda_fp16.h>
#include <mma.h>
#include <cstdint>

using namespace nvcuda;

#define B_  2
#define S_  2048
#define D_  2048
#define H_  16
#define HD_ 128
#define M_  (B_ * S_)      // 4096 token rows

// ---------------- scratch (device globals; no dynamic allocation) ----------------
__device__ __align__(256) __half g_h   [(size_t)M_ * D_];
__device__ __align__(256) __half g_qkvh[(size_t)M_ * 3 * D_];
__device__ __align__(256) __half g_attn[(size_t)M_ * D_];
__device__ __align__(256) float  g_x1  [(size_t)M_ * D_];
__device__ __align__(256) __half g_ffn [(size_t)M_ * 4 * D_];
__device__ __align__(256) __half g_wqkv[(size_t)3 * D_ * D_];
__device__ __align__(256) __half g_wout[(size_t)D_ * D_];
__device__ __align__(256) __half g_wfc1[(size_t)4 * D_ * D_];
__device__ __align__(256) __half g_wfc2[(size_t)D_ * 4 * D_];

#define QSCALE 0.08838834764831845f      // 1/sqrt(128)

// ---------------- cp.async helpers ----------------
__device__ __forceinline__ void cp_async16s(unsigned smem_dst, const void* gmem_src) {
    asm volatile("cp.async.cg.shared.global [%0], [%1], 16;\n" :: "r"(smem_dst), "l"(gmem_src));
}
__device__ __forceinline__ void cp_commit() { asm volatile("cp.async.commit_group;\n"); }
__device__ __forceinline__ void cp_wait0()  { asm volatile("cp.async.wait_group 0;\n"); }
__device__ __forceinline__ void cp_wait1()  { asm volatile("cp.async.wait_group 1;\n"); }

// ---------------- weight fp32 -> fp16 ----------------
__global__ void cvt_f2h_kernel(const float* __restrict__ in, __half* __restrict__ out, int n4) {
    int i = blockIdx.x * 256 + threadIdx.x;
    if (i >= n4) return;
    float4 v = ((const float4*)in)[i];
    ((__half2*)out)[i * 2]     = __floats2half2_rn(v.x, v.y);
    ((__half2*)out)[i * 2 + 1] = __floats2half2_rn(v.z, v.w);
}

// ---------------- rmsnorm (fp16 output) ----------------
__global__ void rmsnorm_kernel(const float* __restrict__ x, const float* __restrict__ g,
                               __half* __restrict__ out) {
    int row = blockIdx.x;
    const float* xr = x + (size_t)row * D_;
    __half* orow = out + (size_t)row * D_;
    float ss = 0.f;
    for (int i = threadIdx.x; i < D_; i += 256) { float v = xr[i]; ss += v * v; }
    __shared__ float red[8];
    #pragma unroll
    for (int o = 16; o > 0; o >>= 1) ss += __shfl_xor_sync(0xffffffffu, ss, o);
    if ((threadIdx.x & 31) == 0) red[threadIdx.x >> 5] = ss;
    __syncthreads();
    if (threadIdx.x < 8) {
        float v = red[threadIdx.x];
        #pragma unroll
        for (int o = 4; o > 0; o >>= 1) v += __shfl_xor_sync(0xffu, v, o);
        if (threadIdx.x == 0) red[0] = v;
    }
    __syncthreads();
    float inv = rsqrtf(red[0] / (float)D_ + 1e-6f);
    for (int i = threadIdx.x; i < D_; i += 256) orow[i] = __float2half(g[i] * xr[i] * inv);
}

// ---------------- fp16 GEMM: C[M,N] = epi(A[M,K] @ B[N,K]^T) ----------------
// Block tile 128x256, BK=64 halfs, 3-stage cp.async pipeline.
// 8 warps (2 x 4); warp tile 64 x 64; 16x16x16 half fragments, fp32 accum.
// ACT: 0 = float C + optional residual; 1 = tanh-gelu -> half C; 2 = plain -> half C.
#define GBM 128
#define GBN 256
#define GBK 64
#define GLD 72
#define A_ST (GBM * GLD)
#define B_ST (GBN * GLD)
#define ST_H (A_ST + B_ST)
#define GT_SMEM_BYTES (3 * ST_H * 2)      // 165888 B

template <int ACT>
__global__ __launch_bounds__(256, 1) void gemm_fp16(const __half* __restrict__ A,
                                                    const __half* __restrict__ Bm,
                                                    void* __restrict__ Cv,
                                                    const float* __restrict__ res,
                                                    int M, int N, int K) {
    extern __shared__ __half smem[];
    unsigned sbase = (unsigned)__cvta_generic_to_shared(smem);

    int tid = threadIdx.x, warp = tid >> 5;
    int wm = warp & 1, wn = warp >> 1;                 // 2 x 4
    int bm = blockIdx.y * GBM, bn = blockIdx.x * GBN;

    wmma::fragment<wmma::accumulator, 16, 16, 16, float> acc[4][4];
    #pragma unroll
    for (int i = 0; i < 4; i++)
        #pragma unroll
        for (int j = 0; j < 4; j++) wmma::fill_fragment(acc[i][j], 0.f);

    const int NT = K / GBK;

    auto load_tile = [&](int t) {
        int st = t % 3;
        unsigned a_s = sbase + (unsigned)(st * ST_H) * 2u;
        unsigned b_s = a_s + A_ST * 2u;
        int k0 = t * GBK;
        #pragma unroll
        for (int i = tid; i < GBM * 8; i += 256) {
            int r = i >> 3, c8 = i & 7;
            cp_async16s(a_s + (unsigned)(r * GLD + c8 * 8) * 2u,
                        &A[(size_t)(bm + r) * K + k0 + c8 * 8]);
        }
        #pragma unroll
        for (int i = tid; i < GBN * 8; i += 256) {
            int r = i >> 3, c8 = i & 7;
            cp_async16s(b_s + (unsigned)(r * GLD + c8 * 8) * 2u,
                        &Bm[(size_t)(bn + r) * K + k0 + c8 * 8]);
        }
        cp_commit();
    };

    load_tile(0);
    if (NT > 1) load_tile(1);

    for (int t = 0; t < NT; t++) {
        if (t + 1 < NT) cp_wait1(); else cp_wait0();
        __syncthreads();
        if (t + 2 < NT) load_tile(t + 2);

        int st = t % 3;
        __half* As = smem + st * ST_H;
        __half* Bs = As + A_ST;

        #pragma unroll
        for (int kk = 0; kk < GBK; kk += 16) {
            wmma::fragment<wmma::matrix_a, 16, 16, 16, __half, wmma::row_major> af[4];
            wmma::fragment<wmma::matrix_b, 16, 16, 16, __half, wmma::col_major> bf[4];
            #pragma unroll
            for (int i = 0; i < 4; i++)
                wmma::load_matrix_sync(af[i], &As[(wm * 64 + i * 16) * GLD + kk], GLD);
            #pragma unroll
            for (int j = 0; j < 4; j++)
                wmma::load_matrix_sync(bf[j], &Bs[(wn * 64 + j * 16) * GLD + kk], GLD);
            #pragma unroll
            for (int i = 0; i < 4; i++)
                #pragma unroll
                for (int j = 0; j < 4; j++)
                    wmma::mma_sync(acc[i][j], af[i], bf[j], acc[i][j]);
        }
        __syncthreads();
    }

    // epilogue: stage through smem (float), fuse residual/gelu
    constexpr int SLD = GBN + 4;
    float* stage = (float*)smem;
    #pragma unroll
    for (int i = 0; i < 4; i++)
        #pragma unroll
        for (int j = 0; j < 4; j++)
            wmma::store_matrix_sync(&stage[(size_t)(wm * 64 + i * 16) * SLD + wn * 64 + j * 16],
                                    acc[i][j], SLD, wmma::mem_row_major);
    __syncthreads();
    for (int i = tid; i < GBM * (GBN / 4); i += 256) {
        int r = i >> 6, c4 = (i & 63) << 2;
        float4 v = *(float4*)&stage[(size_t)r * SLD + c4];
        if (ACT == 1) {
            float* p = (float*)&v;
            #pragma unroll
            for (int e = 0; e < 4; e++) {
                float xx = p[e];
                float th = tanhf(0.7978845608028654f * (xx + 0.044715f * xx * xx * xx));
                p[e] = 0.5f * xx * (1.f + th);
            }
        }
        if (ACT == 1 || ACT == 2) {
            __half* Ch = (__half*)Cv;
            __half2* dst = (__half2*)&Ch[(size_t)(bm + r) * N + bn + c4];
            dst[0] = __floats2half2_rn(v.x, v.y);
            dst[1] = __floats2half2_rn(v.z, v.w);
        } else {
            if (res) {
                const float4 rv = *(const float4*)&res[(size_t)(bm + r) * N + bn + c4];
                v.x += rv.x; v.y += rv.y; v.z += rv.z; v.w += rv.w;
            }
            *(float4*)&((float*)Cv)[(size_t)(bm + r) * N + bn + c4] = v;
        }
    }
}

// ---------------- RoPE on fp16 qkv (fp32 math; q-scale folded in) ----------------
__global__ void rope_h_kernel(__half* __restrict__ qkv, const float* __restrict__ cs,
                              const float* __restrict__ sn) {
    int idx = blockIdx.x * 256 + threadIdx.x;
    if (idx >= M_ * H_ * 64) return;
    int d = idx & 63;
    int h = (idx >> 6) & 15;
    int row = idx >> 10;
    int s = row & (S_ - 1);
    float c0 = cs[s * HD_ + d],      s0 = sn[s * HD_ + d];
    float c1 = cs[s * HD_ + d + 64], s1 = sn[s * HD_ + d + 64];
    #pragma unroll
    for (int p = 0; p < 2; p++) {                 // p=0: q (scaled), p=1: k
        size_t base = (size_t)row * (3 * D_) + (size_t)p * D_ + h * HD_;
        float a = __half2float(qkv[base + d]);
        float b = __half2float(qkv[base + d + 64]);
        float o0 = a * c0 - b * s0;
        float o1 = b * c1 + a * s1;
        if (p == 0) { o0 *= QSCALE; o1 *= QSCALE; }
        qkv[base + d]      = __float2half(o0);
        qkv[base + d + 64] = __float2half(o1);
    }
}

// ---------------- flash attention (causal), fp16 MMA, cp.async K/V double buffer ----------------
struct FaSmem {
    __half Qh[64][136];
    __half Kh[2][64][136];
    __half Vh[2][64][136];
    float  Sf[64][68];
    __half Ph[64][72];
    float  Os[64][128];
    float  Ot[64][132];
    float  mrow[64], lrow[64], alpha[64];
};

__global__ __launch_bounds__(256) void flash_kernel(const __half* __restrict__ qkv,
                                                    __half* __restrict__ attn) {
    extern __shared__ char smem_raw[];
    FaSmem& s = *reinterpret_cast<FaSmem*>(smem_raw);
    int b = blockIdx.z, h = blockIdx.y, q0 = blockIdx.x * 64;
    int tid = threadIdx.x, warp = tid >> 5;
    int wm = warp >> 1, wn = warp & 1;          // 4 x 2

    size_t qbase = ((size_t)(b * S_ + q0)) * (3 * D_) + h * HD_;
    for (int i = tid; i < 64 * 16; i += 256) {
        int r = i >> 4, c8 = (i & 15) << 3;
        *(uint4*)&s.Qh[r][c8] = *(const uint4*)&qkv[qbase + (size_t)r * (3 * D_) + c8];
    }
    for (int i = tid; i < 64 * 128; i += 256) ((float*)s.Os)[i] = 0.f;
    if (tid < 64) { s.mrow[tid] = -1e30f; s.lrow[tid] = 0.f; }

    size_t kbase = ((size_t)(b * S_)) * (3 * D_) + D_ + h * HD_;
    size_t vbase = kbase + D_;
    const int NTI = q0 / 64 + 1;                // causal tile count

    unsigned k_s = (unsigned)__cvta_generic_to_shared(&s.Kh[0][0][0]);
    unsigned v_s = (unsigned)__cvta_generic_to_shared(&s.Vh[0][0][0]);
    const unsigned BUFB = 64 * 136 * 2;         // bytes per K (or V) buffer

    auto load_kv = [&](int t) {                 // tile t -> buffer t&1
        unsigned kb = k_s + (unsigned)(t & 1) * BUFB;
        unsigned vb = v_s + (unsigned)(t & 1) * BUFB;
        int j0 = t * 64;
        #pragma unroll
        for (int i = tid; i < 64 * 16; i += 256) {
            int r = i >> 4, c8 = (i & 15) << 3;
            unsigned off = (unsigned)(r * 136 + c8) * 2u;
            cp_async16s(kb + off, &qkv[kbase + (size_t)(j0 + r) * (3 * D_) + c8]);
            cp_async16s(vb + off, &qkv[vbase + (size_t)(j0 + r) * (3 * D_) + c8]);
        }
        cp_commit();
    };

    load_kv(0);

    for (int t = 0; t < NTI; t++) {
        cp_wait0();
        __syncthreads();                         // tile t resident; iter t-1 fully done
        if (t + 1 < NTI) load_kv(t + 1);         // overlaps with compute of tile t
        int buf = t & 1;
        int j0 = t * 64;

        // S = Q K^T  (64x64, K=128); warp tile 16x32
        wmma::fragment<wmma::accumulator, 16, 16, 16, float> accs[2];
        wmma::fill_fragment(accs[0], 0.f);
        wmma::fill_fragment(accs[1], 0.f);
        #pragma unroll
        for (int kk = 0; kk < 128; kk += 16) {
            wmma::fragment<wmma::matrix_a, 16, 16, 16, __half, wmma::row_major> af;
            wmma::load_matrix_sync(af, &s.Qh[wm * 16][kk], 136);
            #pragma unroll
            for (int j = 0; j < 2; j++) {
                wmma::fragment<wmma::matrix_b, 16, 16, 16, __half, wmma::col_major> bf;
                wmma::load_matrix_sync(bf, &s.Kh[buf][wn * 32 + j * 16][kk], 136);
                wmma::mma_sync(accs[j], af, bf, accs[j]);
            }
        }
        wmma::store_matrix_sync(&s.Sf[wm * 16][wn * 32],      accs[0], 68, wmma::mem_row_major);
        wmma::store_matrix_sync(&s.Sf[wm * 16][wn * 32 + 16], accs[1], 68, wmma::mem_row_major);
        __syncthreads();

        // online softmax: 4 threads per row; write P as fp16
        {
            int r = tid >> 2, part = tid & 3;
            bool diag = (j0 == q0);
            float vals[16];
            float mx = -1e30f;
            #pragma unroll
            for (int c = 0; c < 16; c++) {
                int cc = part * 16 + c;
                float v = s.Sf[r][cc];
                if (diag && cc > r) v = -1e30f;
                vals[c] = v;
                mx = fmaxf(mx, v);
            }
            mx = fmaxf(mx, __shfl_xor_sync(0xffffffffu, mx, 1));
            mx = fmaxf(mx, __shfl_xor_sync(0xffffffffu, mx, 2));
            float newm = fmaxf(s.mrow[r], mx);
            float sum = 0.f;
            #pragma unroll
            for (int c = 0; c < 16; c++) {
                float p = (vals[c] <= -1e29f) ? 0.f : __expf(vals[c] - newm);
                s.Ph[r][part * 16 + c] = __float2half(p);
                sum += p;
            }
            sum += __shfl_xor_sync(0xffffffffu, sum, 1);
            sum += __shfl_xor_sync(0xffffffffu, sum, 2);
            if (part == 0) {
                float al = __expf(s.mrow[r] - newm);
                s.alpha[r] = al;
                s.lrow[r] = s.lrow[r] * al + sum;
                s.mrow[r] = newm;
            }
        }
        __syncthreads();

        // PV (64x128, K=64); warp tile 16x64 -> Ot scratch
        wmma::fragment<wmma::accumulator, 16, 16, 16, float> acco[4];
        #pragma unroll
        for (int j = 0; j < 4; j++) wmma::fill_fragment(acco[j], 0.f);
        #pragma unroll
        for (int kk = 0; kk < 64; kk += 16) {
            wmma::fragment<wmma::matrix_a, 16, 16, 16, __half, wmma::row_major> af;
            wmma::load_matrix_sync(af, &s.Ph[wm * 16][kk], 72);
            #pragma unroll
            for (int j = 0; j < 4; j++) {
                wmma::fragment<wmma::matrix_b, 16, 16, 16, __half, wmma::row_major> bf;
                wmma::load_matrix_sync(bf, &s.Vh[buf][kk][wn * 64 + j * 16], 136);
                wmma::mma_sync(acco[j], af, bf, acco[j]);
            }
        }
        #pragma unroll
        for (int j = 0; j < 4; j++)
            wmma::store_matrix_sync(&s.Ot[wm * 16][wn * 64 + j * 16], acco[j], 132,
                                    wmma::mem_row_major);
        __syncthreads();

        for (int i = tid; i < 64 * 128; i += 256) {
            int r = i >> 7, c = i & 127;
            s.Os[r][c] = s.Os[r][c] * s.alpha[r] + s.Ot[r][c];
        }
    }
    __syncthreads();

    size_t obase = ((size_t)(b * S_ + q0)) * D_ + h * HD_;
    for (int i = tid; i < 64 * 128; i += 256) {
        int r = i >> 7, c = i & 127;
        attn[obase + (size_t)r * D_ + c] = __float2half(s.Os[r][c] / s.lrow[r]);
    }
}

// ---------------- launch ----------------
extern "C" void kernel_launch(void* const* d_in, const int* in_sizes, int n_in,
                              void* d_out, int out_size) {
    const float* x     = (const float*)d_in[0];
    const float* cs    = (const float*)d_in[1];
    const float* sn    = (const float*)d_in[2];
    const float* g1    = (const float*)d_in[3];
    const float* g2    = (const float*)d_in[4];
    const float* w_qkv = (const float*)d_in[5];
    const float* w_out = (const float*)d_in[6];
    const float* w_fc1 = (const float*)d_in[7];
    const float* w_fc2 = (const float*)d_in[8];
    float* out = (float*)d_out;

    __half *h, *qkvh, *attn, *ffn, *wq, *wo, *w1, *w2;
    float *x1;
    cudaGetSymbolAddress((void**)&h,    g_h);
    cudaGetSymbolAddress((void**)&qkvh, g_qkvh);
    cudaGetSymbolAddress((void**)&attn, g_attn);
    cudaGetSymbolAddress((void**)&x1,   g_x1);
    cudaGetSymbolAddress((void**)&ffn,  g_ffn);
    cudaGetSymbolAddress((void**)&wq,   g_wqkv);
    cudaGetSymbolAddress((void**)&wo,   g_wout);
    cudaGetSymbolAddress((void**)&w1,   g_wfc1);
    cudaGetSymbolAddress((void**)&w2,   g_wfc2);

    cudaFuncSetAttribute((const void*)gemm_fp16<0>,
                         cudaFuncAttributeMaxDynamicSharedMemorySize, GT_SMEM_BYTES);
    cudaFuncSetAttribute((const void*)gemm_fp16<1>,
                         cudaFuncAttributeMaxDynamicSharedMemorySize, GT_SMEM_BYTES);
    cudaFuncSetAttribute((const void*)gemm_fp16<2>,
                         cudaFuncAttributeMaxDynamicSharedMemorySize, GT_SMEM_BYTES);
    cudaFuncSetAttribute((const void*)flash_kernel,
                         cudaFuncAttributeMaxDynamicSharedMemorySize, (int)sizeof(FaSmem));

    // 0) weights -> fp16 copies
    cvt_f2h_kernel<<<(3 * D_ * D_ / 4 + 255) / 256, 256>>>(w_qkv, wq, 3 * D_ * D_ / 4);
    cvt_f2h_kernel<<<(D_ * D_ / 4 + 255) / 256, 256>>>(w_out, wo, D_ * D_ / 4);
    cvt_f2h_kernel<<<(4 * D_ * D_ / 4 + 255) / 256, 256>>>(w_fc1, w1, 4 * D_ * D_ / 4);
    cvt_f2h_kernel<<<(4 * D_ * D_ / 4 + 255) / 256, 256>>>(w_fc2, w2, 4 * D_ * D_ / 4);

    // 1) rmsnorm1 -> fp16 h
    rmsnorm_kernel<<<M_, 256>>>(x, g1, h);
    // 2) qkv = h @ wq^T -> fp16 (plain half epilogue)
    gemm_fp16<2><<<dim3(6144 / GBN, M_ / GBM), 256, GT_SMEM_BYTES>>>(h, wq, (void*)qkvh,
                                                                     nullptr, M_, 3 * D_, D_);
    // 3) rope (+ q-scale) on fp16 qkv
    rope_h_kernel<<<(M_ * H_ * 64) / 256, 256>>>(qkvh, cs, sn);
    // 4) causal flash attention (fp16 in/out, pipelined K/V)
    flash_kernel<<<dim3(S_ / 64, H_, B_), 256, sizeof(FaSmem)>>>(qkvh, attn);
    // 5) x1 = x + attn @ wo^T
    gemm_fp16<0><<<dim3(D_ / GBN, M_ / GBM), 256, GT_SMEM_BYTES>>>(attn, wo, (void*)x1,
                                                                   x, M_, D_, D_);
    // 6) rmsnorm2 -> fp16 h
    rmsnorm_kernel<<<M_, 256>>>(x1, g2, h);
    // 7) ffn = gelu(h @ w1^T) -> fp16
    gemm_fp16<1><<<dim3(4 * D_ / GBN, M_ / GBM), 256, GT_SMEM_BYTES>>>(h, w1, (void*)ffn,
                                                                       nullptr, M_, 4 * D_, D_);
    // 8) out = x1 + ffn @ w2^T
    gemm_fp16<0><<<dim3(D_ / GBN, M_ / GBM), 256, GT_SMEM_BYTES>>>(ffn, w2, (void*)out,
                                                                   x1, M_, D_, 4 * D_);
}